// round 1
// baseline (speedup 1.0000x reference)
#include <cuda_runtime.h>

#define HH   128
#define WW   128
#define CINC 64
#define COUT 64
#define BB   16
#define NN   8

#define TH  16   // tile rows per block
#define TW  32   // tile cols per block
#define TCO 16   // output channels per block
#define SXS 35   // smem row stride (coprime-ish with 32 banks)

// Scratch (device globals — no allocation allowed)
__device__ float g_weights[BB * NN];
__device__ float g_beff[BB * COUT];
__device__ float g_weff[BB * CINC * COUT * 9];   // layout [b][ci][co][9]

// ---------------------------------------------------------------------------
// Kernel 1: softmax selector weights + effective bias. One warp per batch.
// ---------------------------------------------------------------------------
__global__ void k_selector(const float* __restrict__ cond,
                           const float* __restrict__ sel_w,
                           const float* __restrict__ sel_b,
                           const float* __restrict__ filt_b) {
    int warp = threadIdx.x >> 5;
    int lane = threadIdx.x & 31;
    int b = warp;            // 16 warps, one per batch
    int n = lane & 7;        // each weight computed 4x redundantly (lanes 0-7,8-15,...)

    float logit = sel_b[n];
    #pragma unroll 8
    for (int k = 0; k < CINC; k++)
        logit += cond[b * CINC + k] * sel_w[n * CINC + k];

    // softmax across groups of 8 lanes
    float m = logit;
    #pragma unroll
    for (int o = 4; o; o >>= 1) m = fmaxf(m, __shfl_xor_sync(0xffffffffu, m, o));
    float e = __expf(logit - m);
    float s = e;
    #pragma unroll
    for (int o = 4; o; o >>= 1) s += __shfl_xor_sync(0xffffffffu, s, o);
    float w = e / s;

    if (lane < 8) g_weights[b * NN + lane] = w;

    // gather all 8 weights into registers
    float wv[NN];
    int base = lane & ~7;
    #pragma unroll
    for (int j = 0; j < 8; j++) wv[j] = __shfl_sync(0xffffffffu, w, base + j);

    // effective bias: beff[b][co] = sum_n w[b,n] * filt_b[n][co]
    float s0 = 0.f, s1 = 0.f;
    #pragma unroll
    for (int j = 0; j < 8; j++) {
        s0 += wv[j] * filt_b[j * COUT + lane];
        s1 += wv[j] * filt_b[j * COUT + lane + 32];
    }
    g_beff[b * COUT + lane]      = s0;
    g_beff[b * COUT + lane + 32] = s1;
}

// ---------------------------------------------------------------------------
// Kernel 2: effective filters. weff[b][ci][co][k] = sum_n w[b,n]*filt_w[n][co][ci][k]
// (ci-major layout so the conv kernel's per-ci filter slice is contiguous)
// ---------------------------------------------------------------------------
__global__ void k_weff(const float* __restrict__ filt_w) {
    int b   = blockIdx.y;
    int idx = blockIdx.x * 256 + threadIdx.x;      // < CINC*COUT*9 = 36864
    int ci  = idx / (COUT * 9);
    int rem = idx % (COUT * 9);
    int co  = rem / 9;
    int k   = rem % 9;
    float s = 0.f;
    #pragma unroll
    for (int n = 0; n < NN; n++)
        s += g_weights[b * NN + n] * filt_w[((n * COUT + co) * CINC + ci) * 9 + k];
    g_weff[(size_t)b * CINC * COUT * 9 + idx] = s;
}

// ---------------------------------------------------------------------------
// Kernel 3: 3x3 SAME conv with per-batch effective filter.
// Block: batch b, 16 output channels, 16x32 spatial tile. 256 threads.
// Thread: 4 co x 8 contiguous-W pixels = 32 accumulators.
// ---------------------------------------------------------------------------
__global__ __launch_bounds__(256) void k_conv(const float* __restrict__ x,
                                              float* __restrict__ out) {
    __shared__ float sx[18 * SXS];   // (TH+2) x (TW+2) input tile, padded stride
    __shared__ float sf[TCO * 9];    // filter slice for this ci

    int tid = threadIdx.x;
    int b   = blockIdx.z >> 2;
    int co0 = (blockIdx.z & 3) * TCO;
    int h0  = blockIdx.y * TH;
    int w0  = blockIdx.x * TW;

    int p   = tid & 63;
    int hh  = p >> 2;          // 0..15 (tile row)
    int w8  = (p & 3) * 8;     // 0,8,16,24 (tile col base)
    int cj0 = (tid >> 6) * 4;  // local co base: 0,4,8,12

    float acc[4][8];
    #pragma unroll
    for (int j = 0; j < 4; j++)
        #pragma unroll
        for (int i = 0; i < 8; i++) acc[j][i] = 0.f;

    const float* xb = x + (size_t)b * CINC * HH * WW;
    const float* wb = g_weff + (size_t)b * CINC * COUT * 9;

    for (int ci = 0; ci < CINC; ci++) {
        const float* xc = xb + ci * HH * WW;
        // load 18x34 input tile (zero-padded halo)
        #pragma unroll
        for (int idx = tid; idx < 18 * 34; idx += 256) {
            int r  = idx / 34, c = idx % 34;
            int gh = h0 - 1 + r, gw = w0 - 1 + c;
            float v = 0.f;
            if ((unsigned)gh < HH && (unsigned)gw < WW) v = xc[gh * WW + gw];
            sx[r * SXS + c] = v;
        }
        // load 16co x 9 filter slice (contiguous in g_weff)
        if (tid < TCO * 9) sf[tid] = wb[(ci * COUT + co0) * 9 + tid];
        __syncthreads();

        // pull the 3x10 input window into registers (shared across the 4 co)
        float xr[3][10];
        #pragma unroll
        for (int dh = 0; dh < 3; dh++)
            #pragma unroll
            for (int k = 0; k < 10; k++)
                xr[dh][k] = sx[(hh + dh) * SXS + w8 + k];

        #pragma unroll
        for (int j = 0; j < 4; j++) {
            const float* f = &sf[(cj0 + j) * 9];
            #pragma unroll
            for (int dh = 0; dh < 3; dh++) {
                float f0 = f[dh * 3 + 0];
                float f1 = f[dh * 3 + 1];
                float f2 = f[dh * 3 + 2];
                #pragma unroll
                for (int i = 0; i < 8; i++)
                    acc[j][i] += xr[dh][i] * f0 + xr[dh][i + 1] * f1 + xr[dh][i + 2] * f2;
            }
        }
        __syncthreads();
    }

    // epilogue: add effective bias, store
    #pragma unroll
    for (int j = 0; j < 4; j++) {
        int co = co0 + cj0 + j;
        float bias = g_beff[b * COUT + co];
        float* o = out + (((size_t)(b * COUT + co) * HH + h0 + hh) * WW + w0 + w8);
        #pragma unroll
        for (int i = 0; i < 8; i++) o[i] = acc[j][i] + bias;
    }
}

// ---------------------------------------------------------------------------
extern "C" void kernel_launch(void* const* d_in, const int* in_sizes, int n_in,
                              void* d_out, int out_size) {
    const float* x      = (const float*)d_in[0];   // [16,64,128,128]
    const float* cond   = (const float*)d_in[1];   // [16,64]
    const float* filt_w = (const float*)d_in[2];   // [8,64,64,3,3]
    const float* filt_b = (const float*)d_in[3];   // [8,64]
    const float* sel_w  = (const float*)d_in[4];   // [8,64]
    const float* sel_b  = (const float*)d_in[5];   // [8]
    float* out = (float*)d_out;                    // [16,64,128,128]

    k_selector<<<1, 512>>>(cond, sel_w, sel_b, filt_b);

    dim3 g2(CINC * COUT * 9 / 256, BB);            // 144 x 16
    k_weff<<<g2, 256>>>(filt_w);

    dim3 g3(WW / TW, HH / TH, BB * (COUT / TCO));  // 4 x 8 x 64
    k_conv<<<g3, 256>>>(x, out);
}

// round 2
// speedup vs baseline: 1.0203x; 1.0203x over previous
#include <cuda_runtime.h>

#define HH   128
#define WW   128
#define CINC 64
#define COUT 64
#define BB   16
#define NN   8

#define TH  16   // tile rows per block
#define TW  32   // tile cols per block
#define TCO 16   // output channels per block
#define SXS 35   // smem row stride (conflict-free for this access pattern)

typedef unsigned long long ull;

// Scratch (device globals — no allocation allowed)
__device__ float g_beff[BB * COUT];
__device__ float g_weff[BB * CINC * COUT * 9];   // layout [b][ci][co][9]

__device__ __forceinline__ ull pack2(float lo, float hi) {
    ull r;
    asm("mov.b64 %0, {%1, %2};" : "=l"(r) : "f"(lo), "f"(hi));
    return r;
}
__device__ __forceinline__ void fma2(ull& d, ull a, ull b) {
    asm("fma.rn.f32x2 %0, %1, %2, %0;" : "+l"(d) : "l"(a), "l"(b));
}
__device__ __forceinline__ void unpack2(float& lo, float& hi, ull v) {
    asm("mov.b64 {%0, %1}, %2;" : "=f"(lo), "=f"(hi) : "l"(v));
}

// ---------------------------------------------------------------------------
// Kernel 1: effective filters + effective bias.
// Each block recomputes the softmax selector weights for its batch locally
// (trivial: 8 x dot-64), then writes a 256-element chunk of weff.
// weff[b][ci][co][k] = sum_n w[b,n] * filt_w[n][co][ci][k]
// ---------------------------------------------------------------------------
__global__ void k_weff(const float* __restrict__ filt_w,
                       const float* __restrict__ cond,
                       const float* __restrict__ sel_w,
                       const float* __restrict__ sel_b,
                       const float* __restrict__ filt_b) {
    __shared__ float sw[NN];
    int b   = blockIdx.y;
    int tid = threadIdx.x;

    if (tid < 32) {
        int n = tid & 7;
        float logit = sel_b[n];
        #pragma unroll 8
        for (int k = 0; k < CINC; k++)
            logit += cond[b * CINC + k] * sel_w[n * CINC + k];
        float m = logit;
        #pragma unroll
        for (int o = 4; o; o >>= 1) m = fmaxf(m, __shfl_xor_sync(0xffffffffu, m, o));
        float e = __expf(logit - m);
        float s = e;
        #pragma unroll
        for (int o = 4; o; o >>= 1) s += __shfl_xor_sync(0xffffffffu, s, o);
        if (tid < 8) sw[tid] = e / s;
    }
    __syncthreads();

    float w[NN];
    #pragma unroll
    for (int n = 0; n < NN; n++) w[n] = sw[n];

    int idx = blockIdx.x * 256 + tid;          // < 36864
    int ci  = idx / (COUT * 9);
    int rem = idx % (COUT * 9);
    int co  = rem / 9;
    int k   = rem % 9;
    float s = 0.f;
    #pragma unroll
    for (int n = 0; n < NN; n++)
        s += w[n] * filt_w[((n * COUT + co) * CINC + ci) * 9 + k];
    g_weff[(size_t)b * CINC * COUT * 9 + idx] = s;

    if (blockIdx.x == 0 && tid < COUT) {
        float sb = 0.f;
        #pragma unroll
        for (int n = 0; n < NN; n++) sb += w[n] * filt_b[n * COUT + tid];
        g_beff[b * COUT + tid] = sb;
    }
}

// ---------------------------------------------------------------------------
// Kernel 2: 3x3 SAME conv with per-batch effective filter, packed f32x2 math.
// Block: batch b, 16 output channels, 16x32 spatial tile. 256 threads.
// Thread: 4 co x 4 pixel-pairs = 16 f32x2 accumulators.
// Double-buffered smem (x tile + duplicated-filter tile), 1 barrier/iter.
// ---------------------------------------------------------------------------
__global__ __launch_bounds__(256, 2) void k_conv(const float* __restrict__ x,
                                                 float* __restrict__ out) {
    __shared__ float  sx[2][18 * SXS];   // (TH+2) x (TW+2) input tile
    __shared__ float2 sf2[2][TCO * 9];   // filter slice, duplicated (f,f)

    int tid = threadIdx.x;
    int b   = blockIdx.z >> 2;
    int co0 = (blockIdx.z & 3) * TCO;
    int h0  = blockIdx.y * TH;
    int w0  = blockIdx.x * TW;

    int p   = tid & 63;
    int hh  = p >> 2;          // 0..15 (tile row)
    int w8  = (p & 3) * 8;     // 0,8,16,24 (tile col base)
    int cj0 = (tid >> 6) * 4;  // local co base: 0,4,8,12

    // --- precompute tile-load geometry (612 elements, <=3 per thread) ---
    int i0 = tid, i1 = tid + 256, i2 = tid + 512;
    bool has2 = (i2 < 18 * 34);
    int r0 = i0 / 34, c0 = i0 % 34;
    int r1 = i1 / 34, c1 = i1 % 34;
    int r2 = has2 ? i2 / 34 : 0, c2 = has2 ? i2 % 34 : 0;
    int gh0 = h0 - 1 + r0, gw0 = w0 - 1 + c0;
    int gh1 = h0 - 1 + r1, gw1 = w0 - 1 + c1;
    int gh2 = h0 - 1 + r2, gw2 = w0 - 1 + c2;
    bool ok0 = (unsigned)gh0 < HH && (unsigned)gw0 < WW;
    bool ok1 = (unsigned)gh1 < HH && (unsigned)gw1 < WW;
    bool ok2 = has2 && (unsigned)gh2 < HH && (unsigned)gw2 < WW;
    int go0 = ok0 ? gh0 * WW + gw0 : 0;
    int go1 = ok1 ? gh1 * WW + gw1 : 0;
    int go2 = ok2 ? gh2 * WW + gw2 : 0;
    int si0 = r0 * SXS + c0, si1 = r1 * SXS + c1, si2 = r2 * SXS + c2;

    const float* xb = x + (size_t)b * CINC * HH * WW;
    const float* wb = g_weff + (size_t)b * CINC * COUT * 9;

    ull acc2[4][4];
    #pragma unroll
    for (int j = 0; j < 4; j++)
        #pragma unroll
        for (int i = 0; i < 4; i++) acc2[j][i] = 0ull;

    // --- prologue: fill buffer 0 ---
    {
        const float* xc = xb;   // ci = 0
        sx[0][si0] = ok0 ? xc[go0] : 0.f;
        sx[0][si1] = ok1 ? xc[go1] : 0.f;
        if (has2) sx[0][si2] = ok2 ? xc[go2] : 0.f;
        if (tid < TCO * 9) {
            float f = wb[(size_t)co0 * 9 + tid];
            sf2[0][tid] = make_float2(f, f);
        }
    }
    __syncthreads();

    for (int ci = 0; ci < CINC; ci++) {
        int cb = ci & 1, nb = cb ^ 1;
        bool more = (ci + 1 < CINC);

        // prefetch ci+1 into registers (LDG issued before compute)
        float pv0 = 0.f, pv1 = 0.f, pv2 = 0.f, pf = 0.f;
        if (more) {
            const float* xc = xb + (size_t)(ci + 1) * HH * WW;
            if (ok0) pv0 = __ldg(xc + go0);
            if (ok1) pv1 = __ldg(xc + go1);
            if (ok2) pv2 = __ldg(xc + go2);
            if (tid < TCO * 9) pf = wb[((size_t)(ci + 1) * COUT + co0) * 9 + tid];
        }

        // compute from buffer cb
        const float* bx = sx[cb];
        const ull*   bf = (const ull*)sf2[cb];
        #pragma unroll
        for (int dh = 0; dh < 3; dh++) {
            float xs[10];
            #pragma unroll
            for (int k = 0; k < 10; k++)
                xs[k] = bx[(hh + dh) * SXS + w8 + k];
            ull xp[9];
            #pragma unroll
            for (int k = 0; k < 9; k++) xp[k] = pack2(xs[k], xs[k + 1]);

            #pragma unroll
            for (int j = 0; j < 4; j++) {
                ull f0 = bf[(cj0 + j) * 9 + dh * 3 + 0];
                ull f1 = bf[(cj0 + j) * 9 + dh * 3 + 1];
                ull f2 = bf[(cj0 + j) * 9 + dh * 3 + 2];
                #pragma unroll
                for (int i = 0; i < 4; i++) {
                    fma2(acc2[j][i], xp[2 * i],     f0);
                    fma2(acc2[j][i], xp[2 * i + 1], f1);
                    fma2(acc2[j][i], xp[2 * i + 2], f2);
                }
            }
        }

        // store prefetched data into the other buffer
        if (more) {
            sx[nb][si0] = pv0;
            sx[nb][si1] = pv1;
            if (has2) sx[nb][si2] = pv2;
            if (tid < TCO * 9) sf2[nb][tid] = make_float2(pf, pf);
        }
        __syncthreads();
    }

    // --- epilogue: add effective bias, vectorized stores ---
    #pragma unroll
    for (int j = 0; j < 4; j++) {
        int co = co0 + cj0 + j;
        float bias = g_beff[b * COUT + co];
        float o8[8];
        #pragma unroll
        for (int i = 0; i < 4; i++) {
            float lo, hi;
            unpack2(lo, hi, acc2[j][i]);
            o8[2 * i]     = lo + bias;
            o8[2 * i + 1] = hi + bias;
        }
        float* op = out + (((size_t)(b * COUT + co) * HH + h0 + hh) * WW + w0 + w8);
        *(float4*)(op)     = make_float4(o8[0], o8[1], o8[2], o8[3]);
        *(float4*)(op + 4) = make_float4(o8[4], o8[5], o8[6], o8[7]);
    }
}

// ---------------------------------------------------------------------------
extern "C" void kernel_launch(void* const* d_in, const int* in_sizes, int n_in,
                              void* d_out, int out_size) {
    const float* x      = (const float*)d_in[0];   // [16,64,128,128]
    const float* cond   = (const float*)d_in[1];   // [16,64]
    const float* filt_w = (const float*)d_in[2];   // [8,64,64,3,3]
    const float* filt_b = (const float*)d_in[3];   // [8,64]
    const float* sel_w  = (const float*)d_in[4];   // [8,64]
    const float* sel_b  = (const float*)d_in[5];   // [8]
    float* out = (float*)d_out;                    // [16,64,128,128]

    dim3 g1(CINC * COUT * 9 / 256, BB);            // 144 x 16
    k_weff<<<g1, 256>>>(filt_w, cond, sel_w, sel_b, filt_b);

    dim3 g2(WW / TW, HH / TH, BB * (COUT / TCO));  // 4 x 8 x 64
    k_conv<<<g2, 256>>>(x, out);
}

// round 3
// speedup vs baseline: 1.3003x; 1.2743x over previous
#include <cuda_runtime.h>

#define HH   128
#define WW   128
#define CINC 64
#define COUT 64
#define BB   16
#define NN   8

#define TH  16   // tile rows per block
#define TW  32   // tile cols per block
#define TCO 16   // output channels per block
#define SXS 35   // smem row stride in float2 units (3*hh+k distinct mod 16)

typedef unsigned long long ull;

// Scratch (device globals — no allocation allowed)
__device__ float g_beff[BB * COUT];
// pair-interleaved effective filters: [b][ci/2][co][k][2]
__device__ float g_weff2[BB * (CINC / 2) * COUT * 9 * 2];

__device__ __forceinline__ ull pack2(float lo, float hi) {
    ull r;
    asm("mov.b64 %0, {%1, %2};" : "=l"(r) : "f"(lo), "f"(hi));
    return r;
}
__device__ __forceinline__ void fma2(ull& d, ull a, ull b) {
    asm("fma.rn.f32x2 %0, %1, %2, %0;" : "+l"(d) : "l"(a), "l"(b));
}
__device__ __forceinline__ void unpack2(float& lo, float& hi, ull v) {
    asm("mov.b64 {%0, %1}, %2;" : "=f"(lo), "=f"(hi) : "l"(v));
}

// ---------------------------------------------------------------------------
// Kernel 1: effective filters (pair-interleaved) + effective bias.
// Each block recomputes the softmax selector weights for its batch locally.
// ---------------------------------------------------------------------------
__global__ void k_weff(const float* __restrict__ filt_w,
                       const float* __restrict__ cond,
                       const float* __restrict__ sel_w,
                       const float* __restrict__ sel_b,
                       const float* __restrict__ filt_b) {
    __shared__ float sw[NN];
    int b   = blockIdx.y;
    int tid = threadIdx.x;

    if (tid < 32) {
        int n = tid & 7;
        float logit = sel_b[n];
        #pragma unroll 8
        for (int k = 0; k < CINC; k++)
            logit += cond[b * CINC + k] * sel_w[n * CINC + k];
        float m = logit;
        #pragma unroll
        for (int o = 4; o; o >>= 1) m = fmaxf(m, __shfl_xor_sync(0xffffffffu, m, o));
        float e = __expf(logit - m);
        float s = e;
        #pragma unroll
        for (int o = 4; o; o >>= 1) s += __shfl_xor_sync(0xffffffffu, s, o);
        if (tid < 8) sw[tid] = e / s;
    }
    __syncthreads();

    float w[NN];
    #pragma unroll
    for (int n = 0; n < NN; n++) w[n] = sw[n];

    int idx = blockIdx.x * 256 + tid;          // < 36864 = CINC*COUT*9
    int ci  = idx / (COUT * 9);
    int rem = idx % (COUT * 9);
    int co  = rem / 9;
    int k   = rem % 9;
    float s = 0.f;
    #pragma unroll
    for (int n = 0; n < NN; n++)
        s += w[n] * filt_w[((n * COUT + co) * CINC + ci) * 9 + k];
    // pair-interleaved store: [b][ci>>1][co][k][ci&1]
    size_t o = ((((size_t)b * (CINC / 2) + (ci >> 1)) * COUT + co) * 9 + k) * 2 + (ci & 1);
    g_weff2[o] = s;

    if (blockIdx.x == 0 && tid < COUT) {
        float sb = 0.f;
        #pragma unroll
        for (int n = 0; n < NN; n++) sb += w[n] * filt_b[n * COUT + tid];
        g_beff[b * COUT + tid] = sb;
    }
}

// ---------------------------------------------------------------------------
// Kernel 2: 3x3 SAME conv, f32x2 with CI-PAIRS in the two lanes.
// Block: batch b, 16 output channels, 16x32 spatial tile. 256 threads.
// Thread: 4 co x 8 pixels; each acc lane sums even/odd ci halves.
// All operands natural LDS.64 — zero pack movs in the inner loop.
// ---------------------------------------------------------------------------
__global__ __launch_bounds__(256, 2) void k_conv(const float* __restrict__ x,
                                                 float* __restrict__ out) {
    __shared__ ull sxp[2][18 * SXS];   // (TH+2) x (TW+2) ci-pair tile
    __shared__ ull sfp[2][TCO * 9];    // filter ci-pair slice

    int tid = threadIdx.x;
    int b   = blockIdx.z >> 2;
    int co0 = (blockIdx.z & 3) * TCO;
    int h0  = blockIdx.y * TH;
    int w0  = blockIdx.x * TW;

    int p   = tid & 63;
    int hh  = p & 15;          // 0..15 (tile row) — conflict-free LDS.64 phases
    int w8  = (p >> 4) * 8;    // 0,8,16,24 (tile col base)
    int cj0 = (tid >> 6) * 4;  // local co base: 0,4,8,12 (warp-uniform)

    // --- tile-load geometry (612 pair-elements, <=3 per thread) ---
    int i0 = tid, i1 = tid + 256, i2 = tid + 512;
    bool has2 = (i2 < 18 * 34);
    int r0 = i0 / 34, c0 = i0 % 34;
    int r1 = i1 / 34, c1 = i1 % 34;
    int r2 = has2 ? i2 / 34 : 0, c2 = has2 ? i2 % 34 : 0;
    int gh0 = h0 - 1 + r0, gw0 = w0 - 1 + c0;
    int gh1 = h0 - 1 + r1, gw1 = w0 - 1 + c1;
    int gh2 = h0 - 1 + r2, gw2 = w0 - 1 + c2;
    bool ok0 = (unsigned)gh0 < HH && (unsigned)gw0 < WW;
    bool ok1 = (unsigned)gh1 < HH && (unsigned)gw1 < WW;
    bool ok2 = has2 && (unsigned)gh2 < HH && (unsigned)gw2 < WW;
    int go0 = ok0 ? gh0 * WW + gw0 : 0;
    int go1 = ok1 ? gh1 * WW + gw1 : 0;
    int go2 = ok2 ? gh2 * WW + gw2 : 0;
    int si0 = r0 * SXS + c0, si1 = r1 * SXS + c1, si2 = r2 * SXS + c2;

    const float* xb = x + (size_t)b * CINC * HH * WW;
    const ull*   wb = (const ull*)g_weff2 + (size_t)b * (CINC / 2) * COUT * 9;
    bool ldf = (tid < TCO * 9);
    size_t fbase = (size_t)co0 * 9 + tid;   // within one ci2 slice: [co][k]

    ull acc2[4][8];
    #pragma unroll
    for (int j = 0; j < 4; j++)
        #pragma unroll
        for (int i = 0; i < 8; i++) acc2[j][i] = 0ull;

    // --- prologue: fill buffer 0 with ci pair (0,1) ---
    {
        const float* xe = xb;                 // ci = 0
        const float* xo = xb + HH * WW;       // ci = 1
        sxp[0][si0] = pack2(ok0 ? xe[go0] : 0.f, ok0 ? xo[go0] : 0.f);
        sxp[0][si1] = pack2(ok1 ? xe[go1] : 0.f, ok1 ? xo[go1] : 0.f);
        if (has2) sxp[0][si2] = pack2(ok2 ? xe[go2] : 0.f, ok2 ? xo[go2] : 0.f);
        if (ldf) sfp[0][tid] = wb[fbase];
    }
    __syncthreads();

    for (int it = 0; it < CINC / 2; it++) {
        int cb = it & 1, nb = cb ^ 1;
        bool more = (it + 1 < CINC / 2);

        // prefetch next ci pair into registers
        float pe0 = 0.f, po0 = 0.f, pe1 = 0.f, po1 = 0.f, pe2 = 0.f, po2 = 0.f;
        ull pf = 0ull;
        if (more) {
            const float* xe = xb + (size_t)(2 * it + 2) * HH * WW;
            const float* xo = xe + HH * WW;
            if (ok0) { pe0 = __ldg(xe + go0); po0 = __ldg(xo + go0); }
            if (ok1) { pe1 = __ldg(xe + go1); po1 = __ldg(xo + go1); }
            if (ok2) { pe2 = __ldg(xe + go2); po2 = __ldg(xo + go2); }
            if (ldf)   pf  = wb[(size_t)(it + 1) * COUT * 9 + fbase];
        }

        // compute from buffer cb — pure LDS.64 + FMA2
        const ull* bx = sxp[cb];
        const ull* bf = sfp[cb];
        #pragma unroll
        for (int dh = 0; dh < 3; dh++) {
            ull xp[10];
            #pragma unroll
            for (int k = 0; k < 10; k++)
                xp[k] = bx[(hh + dh) * SXS + w8 + k];

            #pragma unroll
            for (int j = 0; j < 4; j++) {
                ull f0 = bf[(cj0 + j) * 9 + dh * 3 + 0];
                ull f1 = bf[(cj0 + j) * 9 + dh * 3 + 1];
                ull f2 = bf[(cj0 + j) * 9 + dh * 3 + 2];
                #pragma unroll
                for (int i = 0; i < 8; i++) {
                    fma2(acc2[j][i], xp[i],     f0);
                    fma2(acc2[j][i], xp[i + 1], f1);
                    fma2(acc2[j][i], xp[i + 2], f2);
                }
            }
        }

        // store prefetched pair into the other buffer
        if (more) {
            sxp[nb][si0] = pack2(pe0, po0);
            sxp[nb][si1] = pack2(pe1, po1);
            if (has2) sxp[nb][si2] = pack2(pe2, po2);
            if (ldf) sfp[nb][tid] = pf;
        }
        __syncthreads();
    }

    // --- epilogue: combine ci lanes, add bias, vectorized stores ---
    #pragma unroll
    for (int j = 0; j < 4; j++) {
        int co = co0 + cj0 + j;
        float bias = g_beff[b * COUT + co];
        float o8[8];
        #pragma unroll
        for (int i = 0; i < 8; i++) {
            float lo, hi;
            unpack2(lo, hi, acc2[j][i]);
            o8[i] = lo + hi + bias;
        }
        float* op = out + (((size_t)(b * COUT + co) * HH + h0 + hh) * WW + w0 + w8);
        *(float4*)(op)     = make_float4(o8[0], o8[1], o8[2], o8[3]);
        *(float4*)(op + 4) = make_float4(o8[4], o8[5], o8[6], o8[7]);
    }
}

// ---------------------------------------------------------------------------
extern "C" void kernel_launch(void* const* d_in, const int* in_sizes, int n_in,
                              void* d_out, int out_size) {
    const float* x      = (const float*)d_in[0];   // [16,64,128,128]
    const float* cond   = (const float*)d_in[1];   // [16,64]
    const float* filt_w = (const float*)d_in[2];   // [8,64,64,3,3]
    const float* filt_b = (const float*)d_in[3];   // [8,64]
    const float* sel_w  = (const float*)d_in[4];   // [8,64]
    const float* sel_b  = (const float*)d_in[5];   // [8]
    float* out = (float*)d_out;                    // [16,64,128,128]

    dim3 g1(CINC * COUT * 9 / 256, BB);            // 144 x 16
    k_weff<<<g1, 256>>>(filt_w, cond, sel_w, sel_b, filt_b);

    dim3 g2(WW / TW, HH / TH, BB * (COUT / TCO));  // 4 x 8 x 64
    k_conv<<<g2, 256>>>(x, out);
}

// round 4
// speedup vs baseline: 1.3012x; 1.0007x over previous
#include <cuda_runtime.h>

#define HH   128
#define WW   128
#define CINC 64
#define COUT 64
#define BB   16
#define NN   8

#define TH  16   // tile rows per block
#define TW  32   // tile cols per block
#define TCO 16   // output channels per block
#define SXS 35   // smem row stride in float2 units (3*hh+k distinct mod 16)

typedef unsigned long long ull;

// Scratch (device globals — no allocation allowed)
__device__ float g_beff[BB * COUT];
// pair-interleaved effective filters: [b][ci/2][co][k][2]
__device__ float g_weff2[BB * (CINC / 2) * COUT * 9 * 2];

__device__ __forceinline__ ull pack2(float lo, float hi) {
    ull r;
    asm("mov.b64 %0, {%1, %2};" : "=l"(r) : "f"(lo), "f"(hi));
    return r;
}
__device__ __forceinline__ void fma2(ull& d, ull a, ull b) {
    asm("fma.rn.f32x2 %0, %1, %2, %0;" : "+l"(d) : "l"(a), "l"(b));
}
__device__ __forceinline__ void unpack2(float& lo, float& hi, ull v) {
    asm("mov.b64 {%0, %1}, %2;" : "=f"(lo), "=f"(hi) : "l"(v));
}

// ---------------------------------------------------------------------------
// Kernel 1: effective filters (pair-interleaved) + effective bias.
// Each block recomputes the softmax selector weights for its batch locally.
// ---------------------------------------------------------------------------
__global__ void k_weff(const float* __restrict__ filt_w,
                       const float* __restrict__ cond,
                       const float* __restrict__ sel_w,
                       const float* __restrict__ sel_b,
                       const float* __restrict__ filt_b) {
    __shared__ float sw[NN];
    int b   = blockIdx.y;
    int tid = threadIdx.x;

    if (tid < 32) {
        int n = tid & 7;
        float logit = sel_b[n];
        #pragma unroll 8
        for (int k = 0; k < CINC; k++)
            logit += cond[b * CINC + k] * sel_w[n * CINC + k];
        float m = logit;
        #pragma unroll
        for (int o = 4; o; o >>= 1) m = fmaxf(m, __shfl_xor_sync(0xffffffffu, m, o));
        float e = __expf(logit - m);
        float s = e;
        #pragma unroll
        for (int o = 4; o; o >>= 1) s += __shfl_xor_sync(0xffffffffu, s, o);
        if (tid < 8) sw[tid] = e / s;
    }
    __syncthreads();

    float w[NN];
    #pragma unroll
    for (int n = 0; n < NN; n++) w[n] = sw[n];

    int idx = blockIdx.x * 256 + tid;          // < 36864 = CINC*COUT*9
    int ci  = idx / (COUT * 9);
    int rem = idx % (COUT * 9);
    int co  = rem / 9;
    int k   = rem % 9;
    float s = 0.f;
    #pragma unroll
    for (int n = 0; n < NN; n++)
        s += w[n] * filt_w[((n * COUT + co) * CINC + ci) * 9 + k];
    // pair-interleaved store: [b][ci>>1][co][k][ci&1]
    size_t o = ((((size_t)b * (CINC / 2) + (ci >> 1)) * COUT + co) * 9 + k) * 2 + (ci & 1);
    g_weff2[o] = s;

    if (blockIdx.x == 0 && tid < COUT) {
        float sb = 0.f;
        #pragma unroll
        for (int n = 0; n < NN; n++) sb += w[n] * filt_b[n * COUT + tid];
        g_beff[b * COUT + tid] = sb;
    }
}

// ---------------------------------------------------------------------------
// Kernel 2: 3x3 SAME conv, f32x2 with CI-PAIRS in the two lanes.
// Block: batch b, 16 output channels, 16x32 spatial tile. 256 threads.
// Thread: 4 co x 8 pixels; each acc lane sums even/odd ci halves.
// All operands natural LDS.64 — zero pack movs in the inner loop.
// ---------------------------------------------------------------------------
__global__ __launch_bounds__(256, 2) void k_conv(const float* __restrict__ x,
                                                 float* __restrict__ out) {
    __shared__ ull sxp[2][18 * SXS];   // (TH+2) x (TW+2) ci-pair tile
    __shared__ ull sfp[2][TCO * 9];    // filter ci-pair slice

    int tid = threadIdx.x;
    int b   = blockIdx.z >> 2;
    int co0 = (blockIdx.z & 3) * TCO;
    int h0  = blockIdx.y * TH;
    int w0  = blockIdx.x * TW;

    int p   = tid & 63;
    int hh  = p & 15;          // 0..15 (tile row) — conflict-free LDS.64 phases
    int w8  = (p >> 4) * 8;    // 0,8,16,24 (tile col base)
    int cj0 = (tid >> 6) * 4;  // local co base: 0,4,8,12 (warp-uniform)

    // --- tile-load geometry (612 pair-elements, <=3 per thread) ---
    int i0 = tid, i1 = tid + 256, i2 = tid + 512;
    bool has2 = (i2 < 18 * 34);
    int r0 = i0 / 34, c0 = i0 % 34;
    int r1 = i1 / 34, c1 = i1 % 34;
    int r2 = has2 ? i2 / 34 : 0, c2 = has2 ? i2 % 34 : 0;
    int gh0 = h0 - 1 + r0, gw0 = w0 - 1 + c0;
    int gh1 = h0 - 1 + r1, gw1 = w0 - 1 + c1;
    int gh2 = h0 - 1 + r2, gw2 = w0 - 1 + c2;
    bool ok0 = (unsigned)gh0 < HH && (unsigned)gw0 < WW;
    bool ok1 = (unsigned)gh1 < HH && (unsigned)gw1 < WW;
    bool ok2 = has2 && (unsigned)gh2 < HH && (unsigned)gw2 < WW;
    int go0 = ok0 ? gh0 * WW + gw0 : 0;
    int go1 = ok1 ? gh1 * WW + gw1 : 0;
    int go2 = ok2 ? gh2 * WW + gw2 : 0;
    int si0 = r0 * SXS + c0, si1 = r1 * SXS + c1, si2 = r2 * SXS + c2;

    const float* xb = x + (size_t)b * CINC * HH * WW;
    const ull*   wb = (const ull*)g_weff2 + (size_t)b * (CINC / 2) * COUT * 9;
    bool ldf = (tid < TCO * 9);
    size_t fbase = (size_t)co0 * 9 + tid;   // within one ci2 slice: [co][k]

    ull acc2[4][8];
    #pragma unroll
    for (int j = 0; j < 4; j++)
        #pragma unroll
        for (int i = 0; i < 8; i++) acc2[j][i] = 0ull;

    // --- prologue: fill buffer 0 with ci pair (0,1) ---
    {
        const float* xe = xb;                 // ci = 0
        const float* xo = xb + HH * WW;       // ci = 1
        sxp[0][si0] = pack2(ok0 ? xe[go0] : 0.f, ok0 ? xo[go0] : 0.f);
        sxp[0][si1] = pack2(ok1 ? xe[go1] : 0.f, ok1 ? xo[go1] : 0.f);
        if (has2) sxp[0][si2] = pack2(ok2 ? xe[go2] : 0.f, ok2 ? xo[go2] : 0.f);
        if (ldf) sfp[0][tid] = wb[fbase];
    }
    __syncthreads();

    for (int it = 0; it < CINC / 2; it++) {
        int cb = it & 1, nb = cb ^ 1;
        bool more = (it + 1 < CINC / 2);

        // prefetch next ci pair into registers
        float pe0 = 0.f, po0 = 0.f, pe1 = 0.f, po1 = 0.f, pe2 = 0.f, po2 = 0.f;
        ull pf = 0ull;
        if (more) {
            const float* xe = xb + (size_t)(2 * it + 2) * HH * WW;
            const float* xo = xe + HH * WW;
            if (ok0) { pe0 = __ldg(xe + go0); po0 = __ldg(xo + go0); }
            if (ok1) { pe1 = __ldg(xe + go1); po1 = __ldg(xo + go1); }
            if (ok2) { pe2 = __ldg(xe + go2); po2 = __ldg(xo + go2); }
            if (ldf)   pf  = wb[(size_t)(it + 1) * COUT * 9 + fbase];
        }

        // compute from buffer cb — pure LDS.64 + FMA2
        const ull* bx = sxp[cb];
        const ull* bf = sfp[cb];
        #pragma unroll
        for (int dh = 0; dh < 3; dh++) {
            ull xp[10];
            #pragma unroll
            for (int k = 0; k < 10; k++)
                xp[k] = bx[(hh + dh) * SXS + w8 + k];

            #pragma unroll
            for (int j = 0; j < 4; j++) {
                ull f0 = bf[(cj0 + j) * 9 + dh * 3 + 0];
                ull f1 = bf[(cj0 + j) * 9 + dh * 3 + 1];
                ull f2 = bf[(cj0 + j) * 9 + dh * 3 + 2];
                #pragma unroll
                for (int i = 0; i < 8; i++) {
                    fma2(acc2[j][i], xp[i],     f0);
                    fma2(acc2[j][i], xp[i + 1], f1);
                    fma2(acc2[j][i], xp[i + 2], f2);
                }
            }
        }

        // store prefetched pair into the other buffer
        if (more) {
            sxp[nb][si0] = pack2(pe0, po0);
            sxp[nb][si1] = pack2(pe1, po1);
            if (has2) sxp[nb][si2] = pack2(pe2, po2);
            if (ldf) sfp[nb][tid] = pf;
        }
        __syncthreads();
    }

    // --- epilogue: combine ci lanes, add bias, vectorized stores ---
    #pragma unroll
    for (int j = 0; j < 4; j++) {
        int co = co0 + cj0 + j;
        float bias = g_beff[b * COUT + co];
        float o8[8];
        #pragma unroll
        for (int i = 0; i < 8; i++) {
            float lo, hi;
            unpack2(lo, hi, acc2[j][i]);
            o8[i] = lo + hi + bias;
        }
        float* op = out + (((size_t)(b * COUT + co) * HH + h0 + hh) * WW + w0 + w8);
        *(float4*)(op)     = make_float4(o8[0], o8[1], o8[2], o8[3]);
        *(float4*)(op + 4) = make_float4(o8[4], o8[5], o8[6], o8[7]);
    }
}

// ---------------------------------------------------------------------------
extern "C" void kernel_launch(void* const* d_in, const int* in_sizes, int n_in,
                              void* d_out, int out_size) {
    const float* x      = (const float*)d_in[0];   // [16,64,128,128]
    const float* cond   = (const float*)d_in[1];   // [16,64]
    const float* filt_w = (const float*)d_in[2];   // [8,64,64,3,3]
    const float* filt_b = (const float*)d_in[3];   // [8,64]
    const float* sel_w  = (const float*)d_in[4];   // [8,64]
    const float* sel_b  = (const float*)d_in[5];   // [8]
    float* out = (float*)d_out;                    // [16,64,128,128]

    dim3 g1(CINC * COUT * 9 / 256, BB);            // 144 x 16
    k_weff<<<g1, 256>>>(filt_w, cond, sel_w, sel_b, filt_b);

    dim3 g2(WW / TW, HH / TH, BB * (COUT / TCO));  // 4 x 8 x 64
    k_conv<<<g2, 256>>>(x, out);
}

// round 6
// speedup vs baseline: 3.8038x; 2.9232x over previous
#include <cuda_runtime.h>
#include <cstdint>

#define BB   16
#define CI   64
#define CO   64
#define HHH  128
#define WWW  128
#define NN   8

#define XBUF 8704    // 4 rows x 16 ci x 136 floats
#define WBUF 10368   // 9 taps x 16 ci x 72 floats
#define SMEM_BYTES ((2 * XBUF + 2 * WBUF) * 4)

// ---------------------------------------------------------------------------
// Device scratch (no allocation allowed)
// ---------------------------------------------------------------------------
__device__ float g_beff[BB * CO];
__device__ float g_wefft[BB * 9 * CI * CO];        // [b][tap][ci][co], tf32-rounded
__device__ float g_xr[BB * CI * HHH * WWW];        // tf32-rounded x (64MB)

// ---------------------------------------------------------------------------
// helpers
// ---------------------------------------------------------------------------
__device__ __forceinline__ float tf32r(float x) {
    float r;
    asm("cvt.rna.tf32.f32 %0, %1;" : "=f"(r) : "f"(x));
    return r;
}
__device__ __forceinline__ uint32_t smem_u32(const void* p) {
    uint32_t a;
    asm("{ .reg .u64 t; cvta.to.shared.u64 t, %1; cvt.u32.u64 %0, t; }"
        : "=r"(a) : "l"(p));
    return a;
}
__device__ __forceinline__ void cpa16(uint32_t dst, const void* src, int zf) {
    asm volatile("cp.async.cg.shared.global [%0], [%1], 16, %2;"
                 :: "r"(dst), "l"(src), "r"(zf) : "memory");
}
__device__ __forceinline__ void mma8(float* d, const uint32_t* a, uint32_t b0, uint32_t b1) {
    asm volatile(
        "mma.sync.aligned.m16n8k8.row.col.f32.tf32.tf32.f32 "
        "{%0,%1,%2,%3}, {%4,%5,%6,%7}, {%8,%9}, {%0,%1,%2,%3};"
        : "+f"(d[0]), "+f"(d[1]), "+f"(d[2]), "+f"(d[3])
        : "r"(a[0]), "r"(a[1]), "r"(a[2]), "r"(a[3]), "r"(b0), "r"(b1));
}

// ---------------------------------------------------------------------------
// Kernel 0: pre-round x to tf32 (unbiased rna)
// ---------------------------------------------------------------------------
__global__ void k_pre(const float4* __restrict__ x) {
    size_t i = (size_t)blockIdx.x * 256 + threadIdx.x;
    float4 v = x[i];
    ((float4*)g_xr)[i] = make_float4(tf32r(v.x), tf32r(v.y), tf32r(v.z), tf32r(v.w));
}

// ---------------------------------------------------------------------------
// Kernel 1: effective filters [b][tap][ci][co] (tf32-rounded) + bias.
// ---------------------------------------------------------------------------
__global__ void k_weff(const float* __restrict__ filt_w,
                       const float* __restrict__ cond,
                       const float* __restrict__ sel_w,
                       const float* __restrict__ sel_b,
                       const float* __restrict__ filt_b) {
    __shared__ float sw[NN];
    int b = blockIdx.y;
    int tid = threadIdx.x;

    if (tid < 32) {
        int n = tid & 7;
        float logit = sel_b[n];
        #pragma unroll 8
        for (int k = 0; k < CI; k++)
            logit += cond[b * CI + k] * sel_w[n * CI + k];
        float m = logit;
        #pragma unroll
        for (int o = 4; o; o >>= 1) m = fmaxf(m, __shfl_xor_sync(0xffffffffu, m, o));
        float e = __expf(logit - m);
        float s = e;
        #pragma unroll
        for (int o = 4; o; o >>= 1) s += __shfl_xor_sync(0xffffffffu, s, o);
        if (tid < 8) sw[tid] = e / s;
    }
    __syncthreads();

    float w[NN];
    #pragma unroll
    for (int n = 0; n < NN; n++) w[n] = sw[n];

    int idx = blockIdx.x * 256 + tid;       // < 36864 = 9*64*64
    int co  = idx & 63;
    int ci  = (idx >> 6) & 63;
    int t   = idx >> 12;                    // 0..8
    float s = 0.f;
    #pragma unroll
    for (int n = 0; n < NN; n++)
        s += w[n] * filt_w[((n * CO + co) * CI + ci) * 9 + t];
    g_wefft[((size_t)(b * 9 + t) * CI + ci) * CO + co] = tf32r(s);

    if (blockIdx.x == 0 && tid < CO) {
        float sb = 0.f;
        #pragma unroll
        for (int n = 0; n < NN; n++) sb += w[n] * filt_b[n * CO + tid];
        g_beff[b * CO + tid] = sb;
    }
}

// ---------------------------------------------------------------------------
// Kernel 2: tf32 mma.sync conv. CTA = (h-pair, batch). 256 threads, 8 warps.
// Warp: M=64co x N=32px (one h row, 32-col quarter). 4 m-tiles x 4 n-tiles.
// K loop: 4 ci-blocks of 16, each serving 9 taps x 2 k8-steps.
// smem: x [ri=4][ci=16][136] (halo cols, stride 136 -> conflict-free),
//       W [tap=9][ci=16][72]  (stride 72 -> conflict-free), double-buffered.
// ---------------------------------------------------------------------------
__device__ __forceinline__ void stage(int b, int h0, int cb,
                                      uint32_t sxb, uint32_t swb, int tid) {
    #pragma unroll
    for (int j = 0; j < 8; j++) {                 // x: 2048 16B chunks
        int id = tid + 256 * j;
        int c4 = id & 31, ri = (id >> 5) & 3, ci = id >> 7;
        int gh = h0 - 1 + ri;
        int ghc = gh < 0 ? 0 : (gh > 127 ? 127 : gh);
        const float* src = g_xr + (((size_t)(b * CI + cb * 16 + ci) * HHH + ghc) * WWW + c4 * 4);
        int zf = ((unsigned)gh < 128u) ? 16 : 0;
        cpa16(sxb + (uint32_t)(ri * 2176 + ci * 136 + 4 + c4 * 4) * 4, src, zf);
    }
    #pragma unroll
    for (int j = 0; j < 9; j++) {                 // W: 2304 16B chunks
        int id = tid + 256 * j;
        int co4 = id & 15, ci = (id >> 4) & 15, t = id >> 8;
        const float* src = g_wefft + ((size_t)((b * 9 + t) * CI + cb * 16 + ci) * CO + co4 * 4);
        cpa16(swb + (uint32_t)((t * 16 + ci) * 72 + co4 * 4) * 4, src, 16);
    }
    asm volatile("cp.async.commit_group;" ::: "memory");
}

__global__ __launch_bounds__(256, 1) void k_conv(float* __restrict__ out) {
    extern __shared__ float smf[];
    float* SX = smf;                  // [2][XBUF]
    float* SW = smf + 2 * XBUF;       // [2][WBUF]
    uint32_t sx_u = smem_u32(SX);
    uint32_t sw_u = smem_u32(SW);

    int tid  = threadIdx.x;
    int warp = tid >> 5;
    int lane = tid & 31;
    int lq = lane & 3, lr = lane >> 2;
    int hl = warp >> 2;               // 0..1: h row within pair
    int colb = (warp & 3) * 32;       // col quarter
    int h0 = blockIdx.x * 2;
    int b  = blockIdx.y;

    // halo zero columns (col -1 at s=3, col 128 at s=132), both buffers
    if (tid < 128) {
        int ri = tid >> 5, ci = (tid >> 1) & 15, sd = tid & 1;
        int off = ri * 2176 + ci * 136 + (sd ? 132 : 3);
        SX[off] = 0.f;
        SX[XBUF + off] = 0.f;
    }

    float d[4][4][4];
    #pragma unroll
    for (int mt = 0; mt < 4; mt++)
        #pragma unroll
        for (int nt = 0; nt < 4; nt++)
            #pragma unroll
            for (int e = 0; e < 4; e++) d[mt][nt][e] = 0.f;

    stage(b, h0, 0, sx_u, sw_u, tid);

    for (int cb = 0; cb < 4; cb++) {
        int buf = cb & 1;
        if (cb < 3) {
            stage(b, h0, cb + 1, sx_u + (buf ^ 1) * XBUF * 4, sw_u + (buf ^ 1) * WBUF * 4, tid);
            asm volatile("cp.async.wait_group 1;" ::: "memory");
        } else {
            asm volatile("cp.async.wait_group 0;" ::: "memory");
        }
        __syncthreads();

        const uint32_t* bxu = (const uint32_t*)(SX + buf * XBUF);
        const uint32_t* bwu = (const uint32_t*)(SW + buf * WBUF);

        #pragma unroll
        for (int kh = 0; kh < 3; kh++) {
            int ri = hl + kh;
            #pragma unroll
            for (int kw = 0; kw < 3; kw++) {
                int t = kh * 3 + kw;
                const uint32_t* xbase = bxu + ri * 2176 + colb + kw + 3 + lr;
                const uint32_t* wbase = bwu + (t * 16 + lq) * 72 + lr;
                #pragma unroll
                for (int sub = 0; sub < 2; sub++) {
                    const uint32_t* wp = wbase + sub * 8 * 72;
                    uint32_t a[4][4];
                    #pragma unroll
                    for (int mt = 0; mt < 4; mt++) {
                        a[mt][0] = wp[mt * 16];
                        a[mt][1] = wp[mt * 16 + 8];
                        a[mt][2] = wp[4 * 72 + mt * 16];
                        a[mt][3] = wp[4 * 72 + mt * 16 + 8];
                    }
                    const uint32_t* xp = xbase + (sub * 8 + lq) * 136;
                    #pragma unroll
                    for (int nt = 0; nt < 4; nt++) {
                        uint32_t b0 = xp[nt * 8];
                        uint32_t b1 = xp[4 * 136 + nt * 8];
                        #pragma unroll
                        for (int mt = 0; mt < 4; mt++)
                            mma8(d[mt][nt], a[mt], b0, b1);
                    }
                }
            }
        }
        __syncthreads();
    }

    // epilogue: bias + store (full 32B sectors per lane quad)
    int h = h0 + hl;
    #pragma unroll
    for (int mt = 0; mt < 4; mt++) {
        int co = mt * 16 + lr;
        float bz0 = g_beff[b * CO + co];
        float bz1 = g_beff[b * CO + co + 8];
        float* r0 = out + (((size_t)(b * CO + co) * HHH + h) * WWW);
        float* r1 = out + (((size_t)(b * CO + co + 8) * HHH + h) * WWW);
        #pragma unroll
        for (int nt = 0; nt < 4; nt++) {
            int col = colb + nt * 8 + 2 * lq;
            *(float2*)(r0 + col) = make_float2(d[mt][nt][0] + bz0, d[mt][nt][1] + bz0);
            *(float2*)(r1 + col) = make_float2(d[mt][nt][2] + bz1, d[mt][nt][3] + bz1);
        }
    }
}

// ---------------------------------------------------------------------------
extern "C" void kernel_launch(void* const* d_in, const int* in_sizes, int n_in,
                              void* d_out, int out_size) {
    const float* x      = (const float*)d_in[0];   // [16,64,128,128]
    const float* cond   = (const float*)d_in[1];   // [16,64]
    const float* filt_w = (const float*)d_in[2];   // [8,64,64,3,3]
    const float* filt_b = (const float*)d_in[3];   // [8,64]
    const float* sel_w  = (const float*)d_in[4];   // [8,64]
    const float* sel_b  = (const float*)d_in[5];   // [8]
    float* out = (float*)d_out;                    // [16,64,128,128]

    cudaFuncSetAttribute(k_conv, cudaFuncAttributeMaxDynamicSharedMemorySize, SMEM_BYTES);

    k_pre<<<BB * CI * HHH * WWW / 1024, 256>>>((const float4*)x);

    dim3 g1(144, BB);                              // 9*64*64/256 x 16
    k_weff<<<g1, 256>>>(filt_w, cond, sel_w, sel_b, filt_b);

    dim3 g2(HHH / 2, BB);                          // 64 h-pairs x 16 batches
    k_conv<<<g2, 256, SMEM_BYTES>>>(out);
}

// round 7
// speedup vs baseline: 5.4547x; 1.4340x over previous
#include <cuda_runtime.h>
#include <cstdint>

#define BB   16
#define CI   64
#define CO   64
#define HHH  128
#define WWW  128
#define NN   8

#define XB 4352              // floats per x buffer: 4 rows x 8 ci x 136
#define WB 4608              // floats per W buffer: 9 t x 4 mt x 32 lanes x 4
#define SMEM_BYTES (2 * (XB + WB) * 4)   // 71,680

// ---------------------------------------------------------------------------
// Device scratch (no allocation allowed)
// ---------------------------------------------------------------------------
__device__ float g_beff[BB * CO];
// fragment-packed effective filters: [b][cb=8][t=9][mt=4][lane=32][4], tf32
__device__ float g_wefft[BB * 8 * 9 * 4 * 32 * 4];

// ---------------------------------------------------------------------------
// helpers
// ---------------------------------------------------------------------------
__device__ __forceinline__ float tf32r(float x) {
    float r;
    asm("cvt.rna.tf32.f32 %0, %1;" : "=f"(r) : "f"(x));
    return r;
}
__device__ __forceinline__ uint32_t smem_u32(const void* p) {
    uint32_t a;
    asm("{ .reg .u64 t; cvta.to.shared.u64 t, %1; cvt.u32.u64 %0, t; }"
        : "=r"(a) : "l"(p));
    return a;
}
__device__ __forceinline__ void cpa16(uint32_t dst, const void* src) {
    asm volatile("cp.async.cg.shared.global [%0], [%1], 16;"
                 :: "r"(dst), "l"(src) : "memory");
}
__device__ __forceinline__ void mma8(float* d, const uint32_t* a, uint32_t b0, uint32_t b1) {
    asm volatile(
        "mma.sync.aligned.m16n8k8.row.col.f32.tf32.tf32.f32 "
        "{%0,%1,%2,%3}, {%4,%5,%6,%7}, {%8,%9}, {%0,%1,%2,%3};"
        : "+f"(d[0]), "+f"(d[1]), "+f"(d[2]), "+f"(d[3])
        : "r"(a[0]), "r"(a[1]), "r"(a[2]), "r"(a[3]), "r"(b0), "r"(b1));
}

// ---------------------------------------------------------------------------
// Kernel 1: effective filters in FRAGMENT-PACKED layout + bias.
// out idx (per b) = ((cb*9 + t)*4 + mt)*128 + lane*4 + e
//   lane = lr*4+lq;  e: (a0,a1,a2,a3) -> co = mt*16+lr+8*(e&1), ci = cb*8+lq+4*(e>>1)
// ---------------------------------------------------------------------------
__global__ void k_weff(const float* __restrict__ filt_w,
                       const float* __restrict__ cond,
                       const float* __restrict__ sel_w,
                       const float* __restrict__ sel_b,
                       const float* __restrict__ filt_b) {
    __shared__ float sw[NN];
    int b = blockIdx.y;
    int tid = threadIdx.x;

    if (tid < 32) {
        int n = tid & 7;
        float logit = sel_b[n];
        #pragma unroll 8
        for (int k = 0; k < CI; k++)
            logit += cond[b * CI + k] * sel_w[n * CI + k];
        float m = logit;
        #pragma unroll
        for (int o = 4; o; o >>= 1) m = fmaxf(m, __shfl_xor_sync(0xffffffffu, m, o));
        float e = __expf(logit - m);
        float s = e;
        #pragma unroll
        for (int o = 4; o; o >>= 1) s += __shfl_xor_sync(0xffffffffu, s, o);
        if (tid < 8) sw[tid] = e / s;
    }
    __syncthreads();

    float w[NN];
    #pragma unroll
    for (int n = 0; n < NN; n++) w[n] = sw[n];

    int idx  = blockIdx.x * 256 + tid;      // < 36864
    int e    = idx & 3;
    int lane = (idx >> 2) & 31;
    int mt   = (idx >> 7) & 3;
    int tcb  = idx >> 9;                    // cb*9 + t, 0..71
    int t    = tcb % 9;
    int cb   = tcb / 9;
    int lr = lane >> 2, lq = lane & 3;
    int co = mt * 16 + lr + 8 * (e & 1);
    int ci = cb * 8 + lq + 4 * (e >> 1);

    float s = 0.f;
    #pragma unroll
    for (int n = 0; n < NN; n++)
        s += w[n] * filt_w[((n * CO + co) * CI + ci) * 9 + t];
    g_wefft[(size_t)b * 36864 + idx] = tf32r(s);

    if (blockIdx.x == 0 && tid < CO) {
        float sb = 0.f;
        #pragma unroll
        for (int n = 0; n < NN; n++) sb += w[n] * filt_b[n * CO + tid];
        g_beff[b * CO + tid] = sb;
    }
}

// ---------------------------------------------------------------------------
// Kernel 2: tf32 mma.sync conv. CTA = (h-pair, batch). 256 threads, 8 warps.
// Warp: M=64co x N=32px (one h row, 32-col quarter). 8 ci-blocks of 8.
// smem: x [2][4ri][8ci][136] (halo cols, bank-safe), W [2][fragment-packed].
// x rounded to tf32 in registers during staging (LDG->cvt->STS).
// ---------------------------------------------------------------------------
__global__ __launch_bounds__(256, 2) void k_conv(const float* __restrict__ x,
                                                 float* __restrict__ out) {
    extern __shared__ float smf[];
    float* SX = smf;                 // [2][XB]
    float* SW = smf + 2 * XB;        // [2][WB]
    uint32_t sw_u = smem_u32(SW);

    int tid  = threadIdx.x;
    int warp = tid >> 5;
    int lane = tid & 31;
    int lq = lane & 3, lr = lane >> 2;
    int hl = warp >> 2;              // h row within pair
    int colb = (warp & 3) * 32;      // col quarter
    int h0 = blockIdx.x * 2;
    int b  = blockIdx.y;

    // halo zero columns (x col -1 at s=3, x col 128 at s=132), both buffers
    if (tid < 128) {
        int sd = tid & 1, ci = (tid >> 1) & 7, ri = (tid >> 4) & 3, bf = tid >> 6;
        SX[bf * XB + ri * 1088 + ci * 136 + (sd ? 132 : 3)] = 0.f;
    }

    // per-thread x staging geometry: 4 float4 chunks
    int c4 = tid & 31, cis = (tid >> 5) & 7;   // col-quarter, ci — fixed; ri = k
    const float* xb = x + (size_t)b * CI * HHH * WWW;
    const float* wbg = g_wefft + (size_t)b * 36864;

    float4 rx[4];
    #define LDGX(cb)                                                            \
    {                                                                           \
        _Pragma("unroll")                                                       \
        for (int k = 0; k < 4; k++) {                                           \
            int gh = h0 - 1 + k;                                                \
            float4 v = make_float4(0.f, 0.f, 0.f, 0.f);                         \
            if ((unsigned)gh < 128u)                                            \
                v = __ldg((const float4*)(xb + ((size_t)((cb) * 8 + cis) * HHH + gh) * WWW + c4 * 4)); \
            rx[k] = make_float4(tf32r(v.x), tf32r(v.y), tf32r(v.z), tf32r(v.w)); \
        }                                                                       \
    }
    #define STSX(bf)                                                            \
    {                                                                           \
        _Pragma("unroll")                                                       \
        for (int k = 0; k < 4; k++)                                             \
            *(float4*)(SX + (bf) * XB + k * 1088 + cis * 136 + 4 + c4 * 4) = rx[k]; \
    }
    #define STGW(cb, bf)                                                        \
    {                                                                           \
        _Pragma("unroll")                                                       \
        for (int k = 0; k < 5; k++) {                                           \
            int c = tid + 256 * k;                                              \
            if (c < 1152)                                                       \
                cpa16(sw_u + ((bf) * WB + c * 4) * 4,                           \
                      wbg + (size_t)(cb) * 4608 + c * 4);                       \
        }                                                                       \
        asm volatile("cp.async.commit_group;" ::: "memory");                    \
    }

    float d[4][4][4];
    #pragma unroll
    for (int mt = 0; mt < 4; mt++)
        #pragma unroll
        for (int nt = 0; nt < 4; nt++)
            #pragma unroll
            for (int e = 0; e < 4; e++) d[mt][nt][e] = 0.f;

    // prologue: fill buffer 0
    LDGX(0);
    STGW(0, 0);
    STSX(0);
    asm volatile("cp.async.wait_group 0;" ::: "memory");
    __syncthreads();

    int xoff = lq * 136 + colb + 3 + lr;

    #pragma unroll 1
    for (int cb = 0; cb < 8; cb++) {
        int buf = cb & 1;
        if (cb < 7) {
            LDGX(cb + 1);
            STGW(cb + 1, buf ^ 1);
        }

        const uint32_t* bxu = (const uint32_t*)(SX + buf * XB);
        const uint4*    bw4 = (const uint4*)(SW + buf * WB);

        #pragma unroll
        for (int kh = 0; kh < 3; kh++) {
            int ri = hl + kh;
            #pragma unroll
            for (int kw = 0; kw < 3; kw++) {
                int t = kh * 3 + kw;
                uint32_t a[4][4];
                #pragma unroll
                for (int mt = 0; mt < 4; mt++) {
                    uint4 v = bw4[(t * 4 + mt) * 32 + lane];
                    a[mt][0] = v.x; a[mt][1] = v.y; a[mt][2] = v.z; a[mt][3] = v.w;
                }
                const uint32_t* xp = bxu + ri * 1088 + xoff + kw;
                #pragma unroll
                for (int nt = 0; nt < 4; nt++) {
                    uint32_t b0 = xp[nt * 8];
                    uint32_t b1 = xp[4 * 136 + nt * 8];
                    #pragma unroll
                    for (int mt = 0; mt < 4; mt++)
                        mma8(d[mt][nt], a[mt], b0, b1);
                }
            }
        }

        if (cb < 7) {
            STSX(buf ^ 1);
            asm volatile("cp.async.wait_group 0;" ::: "memory");
        }
        __syncthreads();
    }

    // epilogue: bias + store
    int h = h0 + hl;
    #pragma unroll
    for (int mt = 0; mt < 4; mt++) {
        int co = mt * 16 + lr;
        float bz0 = g_beff[b * CO + co];
        float bz1 = g_beff[b * CO + co + 8];
        float* r0 = out + (((size_t)(b * CO + co) * HHH + h) * WWW);
        float* r1 = out + (((size_t)(b * CO + co + 8) * HHH + h) * WWW);
        #pragma unroll
        for (int nt = 0; nt < 4; nt++) {
            int col = colb + nt * 8 + 2 * lq;
            *(float2*)(r0 + col) = make_float2(d[mt][nt][0] + bz0, d[mt][nt][1] + bz0);
            *(float2*)(r1 + col) = make_float2(d[mt][nt][2] + bz1, d[mt][nt][3] + bz1);
        }
    }
}

// ---------------------------------------------------------------------------
extern "C" void kernel_launch(void* const* d_in, const int* in_sizes, int n_in,
                              void* d_out, int out_size) {
    const float* x      = (const float*)d_in[0];   // [16,64,128,128]
    const float* cond   = (const float*)d_in[1];   // [16,64]
    const float* filt_w = (const float*)d_in[2];   // [8,64,64,3,3]
    const float* filt_b = (const float*)d_in[3];   // [8,64]
    const float* sel_w  = (const float*)d_in[4];   // [8,64]
    const float* sel_b  = (const float*)d_in[5];   // [8]
    float* out = (float*)d_out;                    // [16,64,128,128]

    cudaFuncSetAttribute(k_conv, cudaFuncAttributeMaxDynamicSharedMemorySize, SMEM_BYTES);

    dim3 g1(144, BB);                              // 36864/256 x 16
    k_weff<<<g1, 256>>>(filt_w, cond, sel_w, sel_b, filt_b);

    dim3 g2(HHH / 2, BB);                          // 64 h-pairs x 16 batches
    k_conv<<<g2, 256, SMEM_BYTES>>>(x, out);
}

// round 8
// speedup vs baseline: 8.3079x; 1.5231x over previous
#include <cuda_runtime.h>
#include <cuda_fp16.h>
#include <cstdint>

#define BB   16
#define CI   64
#define CO   64
#define HHH  128
#define WWW  128
#define NN   8

#define XBU 4352             // uint32 per x buffer: 4 ri x 8 ci2 x 136 (half2)
#define WBU 4608             // uint32 per W buffer: 9 t x 4 mt x 32 lanes x 4 regs
#define SMEM_BYTES (2 * (XBU + WBU) * 4)   // 71,680

// ---------------------------------------------------------------------------
// Device scratch (no allocation allowed)
// ---------------------------------------------------------------------------
__device__ float g_beff[BB * CO];
// fragment-packed fp16 filters: [b][cb=4][t=9][mt=4][lane=32][4 regs] (half2 each)
__device__ uint32_t g_wefft[BB * 4 * 9 * 4 * 32 * 4];

// ---------------------------------------------------------------------------
// helpers
// ---------------------------------------------------------------------------
__device__ __forceinline__ uint32_t smem_u32(const void* p) {
    uint32_t a;
    asm("{ .reg .u64 t; cvta.to.shared.u64 t, %1; cvt.u32.u64 %0, t; }"
        : "=r"(a) : "l"(p));
    return a;
}
__device__ __forceinline__ void cpa16(uint32_t dst, const void* src) {
    asm volatile("cp.async.cg.shared.global [%0], [%1], 16;"
                 :: "r"(dst), "l"(src) : "memory");
}
__device__ __forceinline__ uint32_t h2pack(float lo, float hi) {
    uint32_t r;
    asm("cvt.rn.f16x2.f32 %0, %2, %1;" : "=r"(r) : "f"(lo), "f"(hi));
    return r;
}
__device__ __forceinline__ void mma16(float* d, const uint32_t* a, uint32_t b0, uint32_t b1) {
    asm volatile(
        "mma.sync.aligned.m16n8k16.row.col.f32.f16.f16.f32 "
        "{%0,%1,%2,%3}, {%4,%5,%6,%7}, {%8,%9}, {%0,%1,%2,%3};"
        : "+f"(d[0]), "+f"(d[1]), "+f"(d[2]), "+f"(d[3])
        : "r"(a[0]), "r"(a[1]), "r"(a[2]), "r"(a[3]), "r"(b0), "r"(b1));
}

// ---------------------------------------------------------------------------
// Kernel 1: effective filters, FRAGMENT-PACKED fp16 + bias.
// uint32 idx (per b) = ((cb*9 + t)*4 + mt)*128 + lane*4 + e   (18432 per b)
//   lr=lane>>2, lq=lane&3; co = mt*16 + lr + 8*(e&1);
//   ci0 = cb*16 + 2*lq + 8*(e>>1); half2 = (W[ci0], W[ci0+1])
// ---------------------------------------------------------------------------
__global__ void k_weff(const float* __restrict__ filt_w,
                       const float* __restrict__ cond,
                       const float* __restrict__ sel_w,
                       const float* __restrict__ sel_b,
                       const float* __restrict__ filt_b) {
    __shared__ float sw[NN];
    int b = blockIdx.y;
    int tid = threadIdx.x;

    if (tid < 32) {
        int n = tid & 7;
        float logit = sel_b[n];
        #pragma unroll 8
        for (int k = 0; k < CI; k++)
            logit += cond[b * CI + k] * sel_w[n * CI + k];
        float m = logit;
        #pragma unroll
        for (int o = 4; o; o >>= 1) m = fmaxf(m, __shfl_xor_sync(0xffffffffu, m, o));
        float e = __expf(logit - m);
        float s = e;
        #pragma unroll
        for (int o = 4; o; o >>= 1) s += __shfl_xor_sync(0xffffffffu, s, o);
        if (tid < 8) sw[tid] = e / s;
    }
    __syncthreads();

    float w[NN];
    #pragma unroll
    for (int n = 0; n < NN; n++) w[n] = sw[n];

    int idx  = blockIdx.x * 256 + tid;      // < 18432
    int e    = idx & 3;
    int lane = (idx >> 2) & 31;
    int mt   = (idx >> 7) & 3;
    int tcb  = idx >> 9;                    // cb*9 + t, 0..35
    int t    = tcb % 9;
    int cb   = tcb / 9;
    int lr = lane >> 2, lq = lane & 3;
    int co  = mt * 16 + lr + 8 * (e & 1);
    int ci0 = cb * 16 + 2 * lq + 8 * (e >> 1);

    float s0 = 0.f, s1 = 0.f;
    #pragma unroll
    for (int n = 0; n < NN; n++) {
        const float* fp = filt_w + ((size_t)(n * CO + co) * CI) * 9 + t;
        s0 += w[n] * fp[(size_t)ci0 * 9];
        s1 += w[n] * fp[(size_t)(ci0 + 1) * 9];
    }
    g_wefft[(size_t)b * 18432 + idx] = h2pack(s0, s1);

    if (blockIdx.x == 0 && tid < CO) {
        float sb = 0.f;
        #pragma unroll
        for (int n = 0; n < NN; n++) sb += w[n] * filt_b[n * CO + tid];
        g_beff[b * CO + tid] = sb;
    }
}

// ---------------------------------------------------------------------------
// Kernel 2: fp16 mma.sync conv. CTA = (h-pair, batch). 256 threads, 8 warps.
// Warp: M=64co x N=32px (one h row, 32-col quarter). 4 ci-blocks of 16.
// smem x: [2][4 ri][8 ci2][136] half2 (ci even in .lo), halo cols at 3 / 132.
// x rounded to fp16 in registers during staging (LDG.128 pair -> cvt -> STS.128).
// ---------------------------------------------------------------------------
__global__ __launch_bounds__(256, 2) void k_conv(const float* __restrict__ x,
                                                 float* __restrict__ out) {
    extern __shared__ uint32_t smu[];
    uint32_t* SX = smu;               // [2][XBU]
    uint32_t* SW = smu + 2 * XBU;     // [2][WBU]
    uint32_t sw_u = smem_u32(SW);

    int tid  = threadIdx.x;
    int warp = tid >> 5;
    int lane = tid & 31;
    int lq = lane & 3, lr = lane >> 2;
    int hl = warp >> 2;               // h row within pair
    int colb = (warp & 3) * 32;       // col quarter
    int h0 = blockIdx.x * 2;
    int b  = blockIdx.y;

    // halo zero columns (col -1 at idx 3, col 128 at idx 132), both buffers
    if (tid < 128) {
        int sd = tid & 1, ci2 = (tid >> 1) & 7, ri = (tid >> 4) & 3, bf = tid >> 6;
        SX[bf * XBU + ri * 1088 + ci2 * 136 + (sd ? 132 : 3)] = 0u;
    }

    // per-thread x staging geometry
    int c4 = tid & 31, ci2s = (tid >> 5) & 7;
    const float* xb  = x + (size_t)b * CI * HHH * WWW;
    const uint32_t* wbg = g_wefft + (size_t)b * 18432;

    uint4 rx[4];
    #define LDGX(cb)                                                            \
    {                                                                           \
        _Pragma("unroll")                                                       \
        for (int k = 0; k < 4; k++) {                                           \
            int gh = h0 - 1 + k;                                                \
            float4 va = make_float4(0.f, 0.f, 0.f, 0.f), vb = va;               \
            if ((unsigned)gh < 128u) {                                          \
                const float* p = xb + ((size_t)((cb) * 16 + 2 * ci2s) * HHH + gh) * WWW + c4 * 4; \
                va = __ldg((const float4*)p);                                   \
                vb = __ldg((const float4*)(p + HHH * WWW));                     \
            }                                                                   \
            rx[k].x = h2pack(va.x, vb.x);                                       \
            rx[k].y = h2pack(va.y, vb.y);                                       \
            rx[k].z = h2pack(va.z, vb.z);                                       \
            rx[k].w = h2pack(va.w, vb.w);                                       \
        }                                                                       \
    }
    #define STSX(bf)                                                            \
    {                                                                           \
        _Pragma("unroll")                                                       \
        for (int k = 0; k < 4; k++)                                             \
            *(uint4*)(SX + (bf) * XBU + k * 1088 + ci2s * 136 + 4 + c4 * 4) = rx[k]; \
    }
    #define STGW(cb, bf)                                                        \
    {                                                                           \
        _Pragma("unroll")                                                       \
        for (int k = 0; k < 5; k++) {                                           \
            int c = tid + 256 * k;                                              \
            if (c < 1152)                                                       \
                cpa16(sw_u + ((bf) * WBU + c * 4) * 4,                          \
                      wbg + (size_t)(cb) * 4608 + c * 4);                       \
        }                                                                       \
        asm volatile("cp.async.commit_group;" ::: "memory");                    \
    }

    float d[4][4][4];
    #pragma unroll
    for (int mt = 0; mt < 4; mt++)
        #pragma unroll
        for (int nt = 0; nt < 4; nt++)
            #pragma unroll
            for (int e = 0; e < 4; e++) d[mt][nt][e] = 0.f;

    // prologue: fill buffer 0
    LDGX(0);
    STGW(0, 0);
    STSX(0);
    asm volatile("cp.async.wait_group 0;" ::: "memory");
    __syncthreads();

    int xoff = lq * 136 + colb + 3 + lr;   // ci2 = lq, col = colb+lr (+kw, +nt*8)

    #pragma unroll 1
    for (int cb = 0; cb < 4; cb++) {
        int buf = cb & 1;
        if (cb < 3) {
            LDGX(cb + 1);
            STGW(cb + 1, buf ^ 1);
        }

        const uint32_t* bxu = SX + buf * XBU;
        const uint4*    bw4 = (const uint4*)(SW + buf * WBU);

        #pragma unroll
        for (int kh = 0; kh < 3; kh++) {
            int ri = hl + kh;
            #pragma unroll
            for (int kw = 0; kw < 3; kw++) {
                int t = kh * 3 + kw;
                uint32_t a[4][4];
                #pragma unroll
                for (int mt = 0; mt < 4; mt++) {
                    uint4 v = bw4[(t * 4 + mt) * 32 + lane];
                    a[mt][0] = v.x; a[mt][1] = v.y; a[mt][2] = v.z; a[mt][3] = v.w;
                }
                const uint32_t* xp = bxu + ri * 1088 + xoff + kw;
                #pragma unroll
                for (int nt = 0; nt < 4; nt++) {
                    uint32_t b0 = xp[nt * 8];              // ci2 = lq
                    uint32_t b1 = xp[4 * 136 + nt * 8];    // ci2 = lq + 4
                    #pragma unroll
                    for (int mt = 0; mt < 4; mt++)
                        mma16(d[mt][nt], a[mt], b0, b1);
                }
            }
        }

        if (cb < 3) {
            STSX(buf ^ 1);
            asm volatile("cp.async.wait_group 0;" ::: "memory");
        }
        __syncthreads();
    }

    // epilogue: bias + store
    int h = h0 + hl;
    #pragma unroll
    for (int mt = 0; mt < 4; mt++) {
        int co = mt * 16 + lr;
        float bz0 = g_beff[b * CO + co];
        float bz1 = g_beff[b * CO + co + 8];
        float* r0 = out + (((size_t)(b * CO + co) * HHH + h) * WWW);
        float* r1 = out + (((size_t)(b * CO + co + 8) * HHH + h) * WWW);
        #pragma unroll
        for (int nt = 0; nt < 4; nt++) {
            int col = colb + nt * 8 + 2 * lq;
            *(float2*)(r0 + col) = make_float2(d[mt][nt][0] + bz0, d[mt][nt][1] + bz0);
            *(float2*)(r1 + col) = make_float2(d[mt][nt][2] + bz1, d[mt][nt][3] + bz1);
        }
    }
}

// ---------------------------------------------------------------------------
extern "C" void kernel_launch(void* const* d_in, const int* in_sizes, int n_in,
                              void* d_out, int out_size) {
    const float* x      = (const float*)d_in[0];   // [16,64,128,128]
    const float* cond   = (const float*)d_in[1];   // [16,64]
    const float* filt_w = (const float*)d_in[2];   // [8,64,64,3,3]
    const float* filt_b = (const float*)d_in[3];   // [8,64]
    const float* sel_w  = (const float*)d_in[4];   // [8,64]
    const float* sel_b  = (const float*)d_in[5];   // [8]
    float* out = (float*)d_out;                    // [16,64,128,128]

    cudaFuncSetAttribute(k_conv, cudaFuncAttributeMaxDynamicSharedMemorySize, SMEM_BYTES);

    dim3 g1(72, BB);                               // 18432/256 x 16
    k_weff<<<g1, 256>>>(filt_w, cond, sel_w, sel_b, filt_b);

    dim3 g2(HHH / 2, BB);                          // 64 h-pairs x 16 batches
    k_conv<<<g2, 256, SMEM_BYTES>>>(x, out);
}